// round 2
// baseline (speedup 1.0000x reference)
#include <cuda_runtime.h>
#include <math.h>

#define HIDDEN 512
#define HEADS  8
#define DK     64
#define BATCH  2
#define NSEQ   2048
#define MROWS  (BATCH*NSEQ)     // 4096
#define BHN    (BATCH*HEADS)    // 16
#define NORMC  0.125f

// Scratch: Q/K/V in [b,h,n,d] layout, interleaved complex (float2). 16MB each.
__device__ float2 g_q[(size_t)BHN * NSEQ * DK];
__device__ float2 g_k[(size_t)BHN * NSEQ * DK];
__device__ float2 g_v[(size_t)BHN * NSEQ * DK];

// ---------------------------------------------------------------------------
// Projection: Y = X @ W^T + b (complex), X [4096,512], W [512,512].
// Output reindexed to [b,h,n,d] float2.
// Tile: BM=64, BN=64, BK=16, 256 threads, 4x4 micro-tile strided by 16.
// ---------------------------------------------------------------------------
__global__ __launch_bounds__(256) void proj_kernel(
    const float* __restrict__ xr, const float* __restrict__ xi,
    const float* __restrict__ Wr, const float* __restrict__ Wi,
    const float* __restrict__ br, const float* __restrict__ bi,
    int which)
{
    __shared__ float Asr[64][17], Asi[64][17];   // [m][k] (+pad: conflict-free)
    __shared__ float Bsr[64][17], Bsi[64][17];   // [n][k]

    float2* out = (which == 0) ? g_q : ((which == 1) ? g_k : g_v);

    const int n0 = blockIdx.x * 64;   // output-column tile
    const int m0 = blockIdx.y * 64;   // output-row tile
    const int tid = threadIdx.x;
    const int tx = tid & 15, ty = tid >> 4;

    float accr[4][4] = {}, acci[4][4] = {};

    for (int k0 = 0; k0 < HIDDEN; k0 += 16) {
        #pragma unroll
        for (int l = 0; l < 4; l++) {
            int idx = tid + l * 256;
            int kk = idx & 15, rr = idx >> 4;
            Asr[rr][kk] = xr[(size_t)(m0 + rr) * HIDDEN + k0 + kk];
            Asi[rr][kk] = xi[(size_t)(m0 + rr) * HIDDEN + k0 + kk];
            Bsr[rr][kk] = Wr[(size_t)(n0 + rr) * HIDDEN + k0 + kk];
            Bsi[rr][kk] = Wi[(size_t)(n0 + rr) * HIDDEN + k0 + kk];
        }
        __syncthreads();

        #pragma unroll
        for (int kk = 0; kk < 16; kk++) {
            float ar[4], ai[4], wr_[4], wi_[4];
            #pragma unroll
            for (int i = 0; i < 4; i++) { ar[i] = Asr[ty + 16*i][kk]; ai[i] = Asi[ty + 16*i][kk]; }
            #pragma unroll
            for (int j = 0; j < 4; j++) { wr_[j] = Bsr[tx + 16*j][kk]; wi_[j] = Bsi[tx + 16*j][kk]; }
            #pragma unroll
            for (int i = 0; i < 4; i++)
                #pragma unroll
                for (int j = 0; j < 4; j++) {
                    accr[i][j] += ar[i] * wr_[j] - ai[i] * wi_[j];
                    acci[i][j] += ar[i] * wi_[j] + ai[i] * wr_[j];
                }
        }
        __syncthreads();
    }

    #pragma unroll
    for (int i = 0; i < 4; i++) {
        int m = m0 + ty + 16*i;
        int bb = m >> 11;          // m / 2048
        int n  = m & 2047;
        #pragma unroll
        for (int j = 0; j < 4; j++) {
            int col = n0 + tx + 16*j;
            int h = col >> 6, d = col & 63;
            float yr = accr[i][j] + br[col];
            float yi = acci[i][j] + bi[col];
            out[(((size_t)bb * HEADS + h) * NSEQ + n) * DK + d] = make_float2(yr, yi);
        }
    }
}

// ---------------------------------------------------------------------------
// Fused attention (flash-style, no max subtraction needed: |s|*0.125 small).
// CTA = 64 queries of one (b,h); loops over 32 key tiles of 64.
// Per-thread 4x4 micro-tile strided by 16 => all SMEM reads broadcast or
// conflict-free (odd padding 65/17).
// ---------------------------------------------------------------------------
__global__ __launch_bounds__(256) void attn_kernel(float* __restrict__ out)
{
    extern __shared__ float smem[];
    float2* Qs = (float2*)smem;            // [64][64]
    float2* Ks = Qs + 64 * 64;             // [64][65] (padded)
    float2* Vs = Ks + 64 * 65;             // [64][65] (padded)
    float*  Ps = (float*)(Vs + 64 * 65);   // [64][65] weights

    const int bh = blockIdx.y;
    const int n0 = blockIdx.x * 64;
    const int tid = threadIdx.x;
    const int tx = tid & 15, ty = tid >> 4;

    const float2* qb = g_q + (size_t)bh * NSEQ * DK + (size_t)n0 * DK;
    const float2* kb = g_k + (size_t)bh * NSEQ * DK;
    const float2* vb = g_v + (size_t)bh * NSEQ * DK;

    for (int idx = tid; idx < 64 * DK; idx += 256) Qs[idx] = qb[idx];

    float o_r[4][4] = {}, o_i[4][4] = {};
    float den[4] = {};

    for (int c0 = 0; c0 < NSEQ; c0 += 64) {
        __syncthreads();   // previous tile's Ps/Ks/Vs reads complete
        #pragma unroll
        for (int l = 0; l < 16; l++) {
            int idx = tid + l * 256;
            int c = idx >> 6, d = idx & 63;
            Ks[c * 65 + d] = kb[(size_t)c0 * DK + idx];
            Vs[c * 65 + d] = vb[(size_t)c0 * DK + idx];
        }
        __syncthreads();

        // S = Q . K^T (complex, no conj)
        float sr[4][4] = {}, si[4][4] = {};
        #pragma unroll 4
        for (int d = 0; d < DK; d++) {
            float2 qv[4], kv[4];
            #pragma unroll
            for (int i = 0; i < 4; i++) qv[i] = Qs[(ty + 16*i) * DK + d];
            #pragma unroll
            for (int j = 0; j < 4; j++) kv[j] = Ks[(tx + 16*j) * 65 + d];
            #pragma unroll
            for (int i = 0; i < 4; i++)
                #pragma unroll
                for (int j = 0; j < 4; j++) {
                    sr[i][j] += qv[i].x * kv[j].x - qv[i].y * kv[j].y;
                    si[i][j] += qv[i].x * kv[j].y + qv[i].y * kv[j].x;
                }
        }

        // w = exp(|s| * NORM); accumulate denominator; stage weights in SMEM
        #pragma unroll
        for (int i = 0; i < 4; i++)
            #pragma unroll
            for (int j = 0; j < 4; j++) {
                float a = sqrtf(sr[i][j] * sr[i][j] + si[i][j] * si[i][j]) * NORMC;
                float w = __expf(a);
                den[i] += w;
                Ps[(ty + 16*i) * 65 + (tx + 16*j)] = w;
            }
        __syncthreads();

        // O += P @ V (real weights x complex V)
        #pragma unroll 8
        for (int c = 0; c < 64; c++) {
            float p[4]; float2 vv[4];
            #pragma unroll
            for (int i = 0; i < 4; i++) p[i] = Ps[(ty + 16*i) * 65 + c];
            #pragma unroll
            for (int j = 0; j < 4; j++) vv[j] = Vs[c * 65 + tx + 16*j];
            #pragma unroll
            for (int i = 0; i < 4; i++)
                #pragma unroll
                for (int j = 0; j < 4; j++) {
                    o_r[i][j] += p[i] * vv[j].x;
                    o_i[i][j] += p[i] * vv[j].y;
                }
        }
    }

    // Reduce denominator across tx (16 partials per query), reuse Ps
    __syncthreads();
    #pragma unroll
    for (int i = 0; i < 4; i++) Ps[(ty + 16*i) * 17 + tx] = den[i];
    __syncthreads();
    #pragma unroll
    for (int i = 0; i < 4; i++) {
        float s = 0.f;
        #pragma unroll
        for (int t = 0; t < 16; t++) s += Ps[(ty + 16*i) * 17 + t];
        den[i] = 1.0f / s;
    }

    // Output: [B, N, D, 2] fp32 == float2 per complex element
    const int bb = bh >> 3, h = bh & 7;
    float2* outv = (float2*)out;
    #pragma unroll
    for (int i = 0; i < 4; i++) {
        int n = n0 + ty + 16*i;
        #pragma unroll
        for (int j = 0; j < 4; j++) {
            int d = tx + 16*j;
            outv[((size_t)bb * NSEQ + n) * HIDDEN + h * DK + d] =
                make_float2(o_r[i][j] * den[i], o_i[i][j] * den[i]);
        }
    }
}

static const int ATTN_SMEM = (64*64 + 64*65 + 64*65) * 8 + 64*65 * 4;  // 115968 B

extern "C" void kernel_launch(void* const* d_in, const int* in_sizes, int n_in,
                              void* d_out, int out_size)
{
    const float* xr  = (const float*)d_in[0];
    const float* xi  = (const float*)d_in[1];
    const float* Wqr = (const float*)d_in[2];
    const float* Wqi = (const float*)d_in[3];
    const float* bqr = (const float*)d_in[4];
    const float* bqi = (const float*)d_in[5];
    const float* Wkr = (const float*)d_in[6];
    const float* Wki = (const float*)d_in[7];
    const float* bkr = (const float*)d_in[8];
    const float* bki = (const float*)d_in[9];
    const float* Wvr = (const float*)d_in[10];
    const float* Wvi = (const float*)d_in[11];
    const float* bvr = (const float*)d_in[12];
    const float* bvi = (const float*)d_in[13];

    cudaFuncSetAttribute(attn_kernel, cudaFuncAttributeMaxDynamicSharedMemorySize, ATTN_SMEM);

    dim3 pb(256), pg(HIDDEN / 64, MROWS / 64);   // (8, 64)
    proj_kernel<<<pg, pb>>>(xr, xi, Wqr, Wqi, bqr, bqi, 0);
    proj_kernel<<<pg, pb>>>(xr, xi, Wkr, Wki, bkr, bki, 1);
    proj_kernel<<<pg, pb>>>(xr, xi, Wvr, Wvi, bvr, bvi, 2);

    dim3 ag(NSEQ / 64, BHN);                     // (32, 16)
    attn_kernel<<<ag, 256, ATTN_SMEM>>>((float*)d_out);
}

// round 3
// speedup vs baseline: 1.3434x; 1.3434x over previous
#include <cuda_runtime.h>
#include <math.h>

#define HIDDEN 512
#define HEADS  8
#define DK     64
#define BATCH  2
#define NSEQ   2048
#define MROWS  (BATCH*NSEQ)     // 4096
#define BHN    (BATCH*HEADS)    // 16
#define NORMC  0.125f

typedef unsigned long long ull;

// ---- packed f32x2 helpers (Blackwell FFMA2 path; ptxas won't emit from C++) ----
__device__ __forceinline__ ull pack2(float x, float y) {
    ull r; asm("mov.b64 %0, {%1,%2};" : "=l"(r) : "f"(x), "f"(y)); return r;
}
__device__ __forceinline__ ull bcast2(float x) {
    ull r; asm("mov.b64 %0, {%1,%1};" : "=l"(r) : "f"(x)); return r;
}
__device__ __forceinline__ float2 unpack2(ull v) {
    float2 f; asm("mov.b64 {%0,%1}, %2;" : "=f"(f.x), "=f"(f.y) : "l"(v)); return f;
}
__device__ __forceinline__ ull ffma2(ull a, ull b, ull c) {
    ull d; asm("fma.rn.f32x2 %0, %1, %2, %3;" : "=l"(d) : "l"(a), "l"(b), "l"(c)); return d;
}
__device__ __forceinline__ ull as_ull(float2 v) {
    ull r; asm("mov.b64 %0, {%1,%2};" : "=l"(r) : "f"(v.x), "f"(v.y)); return r;
}

// Scratch: Q/K/V in [b,h,n,d] layout, interleaved complex (float2). 16MB each.
__device__ float2 g_q[(size_t)BHN * NSEQ * DK];
__device__ float2 g_k[(size_t)BHN * NSEQ * DK];
__device__ float2 g_v[(size_t)BHN * NSEQ * DK];

// ---------------------------------------------------------------------------
// Projection: Y = X @ W^T + b (complex). Packed-accumulator scheme:
//   acc1 += (ar,ar)*(wr,wi) ; acc2 += (ai,ai)*(wr,wi)
//   re = acc1.x - acc2.y ;  im = acc1.y + acc2.x
// ---------------------------------------------------------------------------
__global__ __launch_bounds__(256) void proj_kernel(
    const float* __restrict__ xr, const float* __restrict__ xi,
    const float* __restrict__ Wr, const float* __restrict__ Wi,
    const float* __restrict__ br, const float* __restrict__ bi,
    int which)
{
    __shared__ float2 Asc[64][17];   // x  (re,im), [m][k], pad -> conflict-free
    __shared__ float2 Bsc[64][17];   // W  (re,im), [n][k]

    float2* out = (which == 0) ? g_q : ((which == 1) ? g_k : g_v);

    const int n0 = blockIdx.x * 64;
    const int m0 = blockIdx.y * 64;
    const int tid = threadIdx.x;
    const int tx = tid & 15, ty = tid >> 4;

    ull acc1[4][4], acc2[4][4];
    #pragma unroll
    for (int i = 0; i < 4; i++)
        #pragma unroll
        for (int j = 0; j < 4; j++) { acc1[i][j] = 0ULL; acc2[i][j] = 0ULL; }

    for (int k0 = 0; k0 < HIDDEN; k0 += 16) {
        #pragma unroll
        for (int l = 0; l < 4; l++) {
            int idx = tid + l * 256;
            int kk = idx & 15, rr = idx >> 4;
            size_t ga = (size_t)(m0 + rr) * HIDDEN + k0 + kk;
            size_t gb = (size_t)(n0 + rr) * HIDDEN + k0 + kk;
            Asc[rr][kk] = make_float2(xr[ga], xi[ga]);
            Bsc[rr][kk] = make_float2(Wr[gb], Wi[gb]);
        }
        __syncthreads();

        #pragma unroll
        for (int kk = 0; kk < 16; kk++) {
            ull arr[4], aii[4], w2[4];
            #pragma unroll
            for (int i = 0; i < 4; i++) {
                float2 a = Asc[ty + 16*i][kk];
                arr[i] = bcast2(a.x); aii[i] = bcast2(a.y);
            }
            #pragma unroll
            for (int j = 0; j < 4; j++) w2[j] = as_ull(Bsc[tx + 16*j][kk]);
            #pragma unroll
            for (int i = 0; i < 4; i++)
                #pragma unroll
                for (int j = 0; j < 4; j++) {
                    acc1[i][j] = ffma2(arr[i], w2[j], acc1[i][j]);
                    acc2[i][j] = ffma2(aii[i], w2[j], acc2[i][j]);
                }
        }
        __syncthreads();
    }

    #pragma unroll
    for (int i = 0; i < 4; i++) {
        int m = m0 + ty + 16*i;
        int bb = m >> 11;
        int n  = m & 2047;
        #pragma unroll
        for (int j = 0; j < 4; j++) {
            int col = n0 + tx + 16*j;
            int h = col >> 6, d = col & 63;
            float2 c1 = unpack2(acc1[i][j]), c2 = unpack2(acc2[i][j]);
            float yr = c1.x - c2.y + br[col];
            float yi = c1.y + c2.x + bi[col];
            out[(((size_t)bb * HEADS + h) * NSEQ + n) * DK + d] = make_float2(yr, yi);
        }
    }
}

// ---------------------------------------------------------------------------
// Fused attention, packed-f32x2 inner loops.
//   S:  s1 += (qx,qx)*(kx,ky) ; s2 += (qy,qy)*(kx,ky)
//       sr = s1.x - s2.y ; si = s1.y + s2.x
//   PV: o  += (p,p)*(vx,vy)
// ---------------------------------------------------------------------------
__global__ __launch_bounds__(256) void attn_kernel(float* __restrict__ out)
{
    extern __shared__ float smem[];
    float2* Qs = (float2*)smem;            // [64][64]
    float2* Ks = Qs + 64 * 64;             // [64][65] (padded)
    float2* Vs = Ks + 64 * 65;             // [64][65] (padded)
    float*  Ps = (float*)(Vs + 64 * 65);   // [64][65] weights

    const int bh = blockIdx.y;
    const int n0 = blockIdx.x * 64;
    const int tid = threadIdx.x;
    const int tx = tid & 15, ty = tid >> 4;

    const float2* qb = g_q + (size_t)bh * NSEQ * DK + (size_t)n0 * DK;
    const float2* kb = g_k + (size_t)bh * NSEQ * DK;
    const float2* vb = g_v + (size_t)bh * NSEQ * DK;

    for (int idx = tid; idx < 64 * DK; idx += 256) Qs[idx] = qb[idx];

    ull o_acc[4][4];
    #pragma unroll
    for (int i = 0; i < 4; i++)
        #pragma unroll
        for (int j = 0; j < 4; j++) o_acc[i][j] = 0ULL;
    float den[4] = {};

    for (int c0 = 0; c0 < NSEQ; c0 += 64) {
        __syncthreads();
        #pragma unroll
        for (int l = 0; l < 16; l++) {
            int idx = tid + l * 256;
            int c = idx >> 6, d = idx & 63;
            Ks[c * 65 + d] = kb[(size_t)c0 * DK + idx];
            Vs[c * 65 + d] = vb[(size_t)c0 * DK + idx];
        }
        __syncthreads();

        // S = Q . K^T (complex, no conj) — packed partials
        ull s1[4][4], s2[4][4];
        #pragma unroll
        for (int i = 0; i < 4; i++)
            #pragma unroll
            for (int j = 0; j < 4; j++) { s1[i][j] = 0ULL; s2[i][j] = 0ULL; }

        #pragma unroll 4
        for (int d = 0; d < DK; d++) {
            ull qxx[4], qyy[4], kv[4];
            #pragma unroll
            for (int i = 0; i < 4; i++) {
                float2 q = Qs[(ty + 16*i) * DK + d];
                qxx[i] = bcast2(q.x); qyy[i] = bcast2(q.y);
            }
            #pragma unroll
            for (int j = 0; j < 4; j++) kv[j] = as_ull(Ks[(tx + 16*j) * 65 + d]);
            #pragma unroll
            for (int i = 0; i < 4; i++)
                #pragma unroll
                for (int j = 0; j < 4; j++) {
                    s1[i][j] = ffma2(qxx[i], kv[j], s1[i][j]);
                    s2[i][j] = ffma2(qyy[i], kv[j], s2[i][j]);
                }
        }

        // w = exp(|s| * NORM); accumulate denominator; stage weights in SMEM
        #pragma unroll
        for (int i = 0; i < 4; i++)
            #pragma unroll
            for (int j = 0; j < 4; j++) {
                float2 c1 = unpack2(s1[i][j]), c2 = unpack2(s2[i][j]);
                float sr = c1.x - c2.y;
                float si = c1.y + c2.x;
                float a = sqrtf(sr * sr + si * si) * NORMC;
                float w = __expf(a);
                den[i] += w;
                Ps[(ty + 16*i) * 65 + (tx + 16*j)] = w;
            }
        __syncthreads();

        // O += P @ V (real weights x complex V) — one FFMA2 per cMAC
        #pragma unroll 8
        for (int c = 0; c < 64; c++) {
            ull p2[4], vv[4];
            #pragma unroll
            for (int i = 0; i < 4; i++) p2[i] = bcast2(Ps[(ty + 16*i) * 65 + c]);
            #pragma unroll
            for (int j = 0; j < 4; j++) vv[j] = as_ull(Vs[c * 65 + tx + 16*j]);
            #pragma unroll
            for (int i = 0; i < 4; i++)
                #pragma unroll
                for (int j = 0; j < 4; j++)
                    o_acc[i][j] = ffma2(p2[i], vv[j], o_acc[i][j]);
        }
    }

    // Reduce denominator across tx (16 partials per query), reuse Ps
    __syncthreads();
    #pragma unroll
    for (int i = 0; i < 4; i++) Ps[(ty + 16*i) * 17 + tx] = den[i];
    __syncthreads();
    #pragma unroll
    for (int i = 0; i < 4; i++) {
        float s = 0.f;
        #pragma unroll
        for (int t = 0; t < 16; t++) s += Ps[(ty + 16*i) * 17 + t];
        den[i] = 1.0f / s;
    }

    // Output: [B, N, D, 2] fp32 == float2 per complex element
    const int bb = bh >> 3, h = bh & 7;
    float2* outv = (float2*)out;
    #pragma unroll
    for (int i = 0; i < 4; i++) {
        int n = n0 + ty + 16*i;
        #pragma unroll
        for (int j = 0; j < 4; j++) {
            int d = tx + 16*j;
            float2 oo = unpack2(o_acc[i][j]);
            outv[((size_t)bb * NSEQ + n) * HIDDEN + h * DK + d] =
                make_float2(oo.x * den[i], oo.y * den[i]);
        }
    }
}

static const int ATTN_SMEM = (64*64 + 64*65 + 64*65) * 8 + 64*65 * 4;  // 115968 B

extern "C" void kernel_launch(void* const* d_in, const int* in_sizes, int n_in,
                              void* d_out, int out_size)
{
    const float* xr  = (const float*)d_in[0];
    const float* xi  = (const float*)d_in[1];
    const float* Wqr = (const float*)d_in[2];
    const float* Wqi = (const float*)d_in[3];
    const float* bqr = (const float*)d_in[4];
    const float* bqi = (const float*)d_in[5];
    const float* Wkr = (const float*)d_in[6];
    const float* Wki = (const float*)d_in[7];
    const float* bkr = (const float*)d_in[8];
    const float* bki = (const float*)d_in[9];
    const float* Wvr = (const float*)d_in[10];
    const float* Wvi = (const float*)d_in[11];
    const float* bvr = (const float*)d_in[12];
    const float* bvi = (const float*)d_in[13];

    cudaFuncSetAttribute(attn_kernel, cudaFuncAttributeMaxDynamicSharedMemorySize, ATTN_SMEM);

    dim3 pb(256), pg(HIDDEN / 64, MROWS / 64);   // (8, 64)
    proj_kernel<<<pg, pb>>>(xr, xi, Wqr, Wqi, bqr, bqi, 0);
    proj_kernel<<<pg, pb>>>(xr, xi, Wkr, Wki, bkr, bki, 1);
    proj_kernel<<<pg, pb>>>(xr, xi, Wvr, Wvi, bvr, bvi, 2);

    dim3 ag(NSEQ / 64, BHN);                     // (32, 16)
    attn_kernel<<<ag, 256, ATTN_SMEM>>>((float*)d_out);
}

// round 9
// speedup vs baseline: 1.4369x; 1.0696x over previous
#include <cuda_runtime.h>
#include <cstdint>
#include <math.h>

#define HIDDEN 512
#define HEADS  8
#define DK     64
#define BATCH  2
#define NSEQ   2048
#define MROWS  (BATCH*NSEQ)     // 4096
#define BHN    (BATCH*HEADS)    // 16
#define NORMC  0.125f
#define TK     32               // keys per attention tile
#define NTILE  (NSEQ/TK)        // 64

typedef unsigned long long ull;
typedef unsigned int uint32;

// ---- packed f32x2 helpers (Blackwell FFMA2 path) ----
__device__ __forceinline__ ull bcast2(float x) {
    ull r; asm("mov.b64 %0, {%1,%1};" : "=l"(r) : "f"(x)); return r;
}
__device__ __forceinline__ float2 unpack2(ull v) {
    float2 f; asm("mov.b64 {%0,%1}, %2;" : "=f"(f.x), "=f"(f.y) : "l"(v)); return f;
}
__device__ __forceinline__ ull ffma2(ull a, ull b, ull c) {
    ull d; asm("fma.rn.f32x2 %0, %1, %2, %3;" : "=l"(d) : "l"(a), "l"(b), "l"(c)); return d;
}
__device__ __forceinline__ ull as_ull(float2 v) {
    ull r; asm("mov.b64 %0, {%1,%2};" : "=l"(r) : "f"(v.x), "f"(v.y)); return r;
}
__device__ __forceinline__ uint32 smem_u32(const void* p) {
    return (uint32)__cvta_generic_to_shared(p);
}
__device__ __forceinline__ void cpa16(uint32 dst, const void* src) {
    asm volatile("cp.async.cg.shared.global [%0], [%1], 16;" :: "r"(dst), "l"(src));
}
#define CPA_COMMIT() asm volatile("cp.async.commit_group;")
#define CPA_WAIT(n)  asm volatile("cp.async.wait_group %0;" :: "n"(n))

// Scratch: Q/K/V in [b,h,n,d] layout, complex interleaved. float4 declaration
// guarantees the 16B alignment cp.async requires; proj views them as float2.
__device__ float4 g_q[(size_t)BHN * NSEQ * DK / 2];
__device__ float4 g_k[(size_t)BHN * NSEQ * DK / 2];
__device__ float4 g_v[(size_t)BHN * NSEQ * DK / 2];

// ---------------------------------------------------------------------------
// Projection: Y = X @ W^T + b (complex), FFMA2 inner loop.
// ---------------------------------------------------------------------------
__global__ __launch_bounds__(256) void proj_kernel(
    const float* __restrict__ xr, const float* __restrict__ xi,
    const float* __restrict__ Wr, const float* __restrict__ Wi,
    const float* __restrict__ br, const float* __restrict__ bi,
    int which)
{
    __shared__ float2 Asc[64][17];
    __shared__ float2 Bsc[64][17];

    float2* out = (float2*)((which == 0) ? g_q : ((which == 1) ? g_k : g_v));

    const int n0 = blockIdx.x * 64;
    const int m0 = blockIdx.y * 64;
    const int tid = threadIdx.x;
    const int tx = tid & 15, ty = tid >> 4;

    ull acc1[4][4], acc2[4][4];
    #pragma unroll
    for (int i = 0; i < 4; i++)
        #pragma unroll
        for (int j = 0; j < 4; j++) { acc1[i][j] = 0ULL; acc2[i][j] = 0ULL; }

    for (int k0 = 0; k0 < HIDDEN; k0 += 16) {
        #pragma unroll
        for (int l = 0; l < 4; l++) {
            int idx = tid + l * 256;
            int kk = idx & 15, rr = idx >> 4;
            size_t ga = (size_t)(m0 + rr) * HIDDEN + k0 + kk;
            size_t gb = (size_t)(n0 + rr) * HIDDEN + k0 + kk;
            Asc[rr][kk] = make_float2(xr[ga], xi[ga]);
            Bsc[rr][kk] = make_float2(Wr[gb], Wi[gb]);
        }
        __syncthreads();

        #pragma unroll
        for (int kk = 0; kk < 16; kk++) {
            ull arr[4], aii[4], w2[4];
            #pragma unroll
            for (int i = 0; i < 4; i++) {
                float2 a = Asc[ty + 16*i][kk];
                arr[i] = bcast2(a.x); aii[i] = bcast2(a.y);
            }
            #pragma unroll
            for (int j = 0; j < 4; j++) w2[j] = as_ull(Bsc[tx + 16*j][kk]);
            #pragma unroll
            for (int i = 0; i < 4; i++)
                #pragma unroll
                for (int j = 0; j < 4; j++) {
                    acc1[i][j] = ffma2(arr[i], w2[j], acc1[i][j]);
                    acc2[i][j] = ffma2(aii[i], w2[j], acc2[i][j]);
                }
        }
        __syncthreads();
    }

    #pragma unroll
    for (int i = 0; i < 4; i++) {
        int m = m0 + ty + 16*i;
        int bb = m >> 11;
        int n  = m & 2047;
        #pragma unroll
        for (int j = 0; j < 4; j++) {
            int col = n0 + tx + 16*j;
            int h = col >> 6, d = col & 63;
            float2 c1 = unpack2(acc1[i][j]), c2 = unpack2(acc2[i][j]);
            float yr = c1.x - c2.y + br[col];
            float yi = c1.y + c2.x + bi[col];
            out[(((size_t)bb * HEADS + h) * NSEQ + n) * DK + d] = make_float2(yr, yi);
        }
    }
}

// ---------------------------------------------------------------------------
// Fused attention: 64 queries x 32-key tiles, cp.async double-buffered K/V,
// 2 CTAs/SM. Packed math:
//   s1 += (qx,qy)*(kx,kx); s2 += (qx,qy)*(ky,ky)
//   re = s1.x - s2.y ; im = s1.y + s2.x
// SMEM (bytes): Qs f4[64*32]=32768 | Ks f4[2][32*33]=33792 |
//               Vs f2[2][32*64]=32768 | Ps f[64*33]=8448  -> 107776 total
// ---------------------------------------------------------------------------
#define KS_STRIDE 33                  // float4 row stride (odd -> conflict-free LDS.128)
#define KS_BUF    (32*KS_STRIDE)      // 1056 float4 per buffer
#define VS_BUF    (32*64)             // 2048 float2 per buffer
#define VS_BUF_BYTES (VS_BUF*8)       // 16384 bytes per V buffer
#define ATTN_SMEM (32768 + 33792 + 32768 + 8448)

__global__ __launch_bounds__(256, 2) void attn_kernel(float* __restrict__ out)
{
    extern __shared__ float smem[];
    float4* Qs = (float4*)smem;                    // [64][32]
    float4* Ks = Qs + 64*32;                       // [2][32][KS_STRIDE]
    float2* Vs = (float2*)(Ks + 2*KS_BUF);         // [2][32][64]
    float*  Ps = (float*)(Vs + 2*VS_BUF);          // [64][33]

    const int bh = blockIdx.y;
    const int n0 = blockIdx.x * 64;
    const int tid = threadIdx.x;
    const int tx = tid & 15, ty = tid >> 4;

    // per-(b,h) base in float4 units (DK complex = 128 floats = 32 float4 per row)
    const float4* qb4 = g_q + ((size_t)bh * NSEQ + n0) * (DK/2);
    const float4* kb4 = g_k + (size_t)bh * NSEQ * (DK/2);
    const float4* vb4 = g_v + (size_t)bh * NSEQ * (DK/2);

    const uint32 qs_b = smem_u32(Qs);
    const uint32 ks_b = smem_u32(Ks);
    const uint32 vs_b = smem_u32(Vs);

    // Prologue: Q (32KB) + tile 0 K/V, one cp.async group
    #pragma unroll
    for (int l = 0; l < 8; l++) {
        int id = tid + l * 256;                    // 0..2047 float4
        cpa16(qs_b + id * 16, qb4 + id);
    }
    {
        #pragma unroll
        for (int l = 0; l < 4; l++) {
            int id = tid + l * 256;                // 0..1023
            int row = id >> 5, dp = id & 31;
            cpa16(ks_b + (row * KS_STRIDE + dp) * 16, kb4 + row * 32 + dp);
            cpa16(vs_b + id * 16, vb4 + id);
        }
    }
    CPA_COMMIT();

    ull o_acc[4][4];
    #pragma unroll
    for (int i = 0; i < 4; i++)
        #pragma unroll
        for (int j = 0; j < 4; j++) o_acc[i][j] = 0ULL;
    float den[4] = {};

    for (int t = 0; t < NTILE; t++) {
        const int cur = t & 1;
        if (t + 1 < NTILE) {
            const int nb = cur ^ 1;
            const float4* kt = kb4 + (size_t)(t + 1) * 1024;
            const float4* vt = vb4 + (size_t)(t + 1) * 1024;
            #pragma unroll
            for (int l = 0; l < 4; l++) {
                int id = tid + l * 256;
                int row = id >> 5, dp = id & 31;
                cpa16(ks_b + (nb * KS_BUF + row * KS_STRIDE + dp) * 16, kt + row * 32 + dp);
                // NOTE: V buffer stride in BYTES (VS_BUF is float2 units) —
                // previous rounds wrote nb*VS_BUF*16 and overran SMEM.
                cpa16(vs_b + nb * VS_BUF_BYTES + id * 16, vt + id);
            }
            CPA_COMMIT();
            CPA_WAIT(1);
        } else {
            CPA_WAIT(0);
        }
        __syncthreads();

        // ---- S = Q . K^T (complex, no conj) over 32 keys ----
        ull s1[4][2], s2[4][2];
        #pragma unroll
        for (int i = 0; i < 4; i++)
            #pragma unroll
            for (int j = 0; j < 2; j++) { s1[i][j] = 0ULL; s2[i][j] = 0ULL; }

        const longlong2* Ksc = (const longlong2*)(Ks + cur * KS_BUF);
        const longlong2* Qsc = (const longlong2*)Qs;

        #pragma unroll 2
        for (int dp = 0; dp < 32; dp++) {
            longlong2 q2[4];
            #pragma unroll
            for (int i = 0; i < 4; i++) q2[i] = Qsc[(ty + 16*i) * 32 + dp];

            ull kxx[2][2], kyy[2][2];
            #pragma unroll
            for (int j = 0; j < 2; j++) {
                longlong2 kv = Ksc[(tx + 16*j) * KS_STRIDE + dp];
                float2 k0 = unpack2((ull)kv.x), k1 = unpack2((ull)kv.y);
                kxx[j][0] = bcast2(k0.x); kyy[j][0] = bcast2(k0.y);
                kxx[j][1] = bcast2(k1.x); kyy[j][1] = bcast2(k1.y);
            }
            #pragma unroll
            for (int i = 0; i < 4; i++)
                #pragma unroll
                for (int j = 0; j < 2; j++) {
                    s1[i][j] = ffma2((ull)q2[i].x, kxx[j][0], s1[i][j]);
                    s2[i][j] = ffma2((ull)q2[i].x, kyy[j][0], s2[i][j]);
                    s1[i][j] = ffma2((ull)q2[i].y, kxx[j][1], s1[i][j]);
                    s2[i][j] = ffma2((ull)q2[i].y, kyy[j][1], s2[i][j]);
                }
        }

        // ---- w = exp(|s| * NORM) -> Ps, accumulate denominator ----
        #pragma unroll
        for (int i = 0; i < 4; i++)
            #pragma unroll
            for (int j = 0; j < 2; j++) {
                float2 c1 = unpack2(s1[i][j]), c2 = unpack2(s2[i][j]);
                float sr = c1.x - c2.y;
                float si = c1.y + c2.x;
                float a = sqrtf(sr * sr + si * si) * NORMC;
                float w = __expf(a);
                den[i] += w;
                Ps[(ty + 16*i) * 33 + (tx + 16*j)] = w;
            }
        __syncthreads();

        // ---- O += P @ V ----
        const float2* Vsc = Vs + cur * VS_BUF;
        #pragma unroll 4
        for (int c = 0; c < 32; c++) {
            ull p2[4], vv[4];
            #pragma unroll
            for (int i = 0; i < 4; i++) p2[i] = bcast2(Ps[(ty + 16*i) * 33 + c]);
            #pragma unroll
            for (int j = 0; j < 4; j++) vv[j] = as_ull(Vsc[c * 64 + tx + 16*j]);
            #pragma unroll
            for (int i = 0; i < 4; i++)
                #pragma unroll
                for (int j = 0; j < 4; j++)
                    o_acc[i][j] = ffma2(p2[i], vv[j], o_acc[i][j]);
        }
        __syncthreads();
    }

    // ---- reduce denominator across tx (16 partials per query row) ----
    #pragma unroll
    for (int i = 0; i < 4; i++) Ps[(ty + 16*i) * 17 + tx] = den[i];
    __syncthreads();
    #pragma unroll
    for (int i = 0; i < 4; i++) {
        float s = 0.f;
        #pragma unroll
        for (int tt = 0; tt < 16; tt++) s += Ps[(ty + 16*i) * 17 + tt];
        den[i] = 1.0f / s;
    }

    // ---- output: [B, N, D, 2] fp32 (= float2 per complex element) ----
    const int bb = bh >> 3, h = bh & 7;
    float2* outv = (float2*)out;
    #pragma unroll
    for (int i = 0; i < 4; i++) {
        int n = n0 + ty + 16*i;
        #pragma unroll
        for (int j = 0; j < 4; j++) {
            int d = tx + 16*j;
            float2 oo = unpack2(o_acc[i][j]);
            outv[((size_t)bb * NSEQ + n) * HIDDEN + h * DK + d] =
                make_float2(oo.x * den[i], oo.y * den[i]);
        }
    }
}

extern "C" void kernel_launch(void* const* d_in, const int* in_sizes, int n_in,
                              void* d_out, int out_size)
{
    const float* xr  = (const float*)d_in[0];
    const float* xi  = (const float*)d_in[1];
    const float* Wqr = (const float*)d_in[2];
    const float* Wqi = (const float*)d_in[3];
    const float* bqr = (const float*)d_in[4];
    const float* bqi = (const float*)d_in[5];
    const float* Wkr = (const float*)d_in[6];
    const float* Wki = (const float*)d_in[7];
    const float* bkr = (const float*)d_in[8];
    const float* bki = (const float*)d_in[9];
    const float* Wvr = (const float*)d_in[10];
    const float* Wvi = (const float*)d_in[11];
    const float* bvr = (const float*)d_in[12];
    const float* bvi = (const float*)d_in[13];

    cudaFuncSetAttribute(attn_kernel, cudaFuncAttributeMaxDynamicSharedMemorySize, ATTN_SMEM);

    dim3 pb(256), pg(HIDDEN / 64, MROWS / 64);   // (8, 64)
    proj_kernel<<<pg, pb>>>(xr, xi, Wqr, Wqi, bqr, bqi, 0);
    proj_kernel<<<pg, pb>>>(xr, xi, Wkr, Wki, bkr, bki, 1);
    proj_kernel<<<pg, pb>>>(xr, xi, Wvr, Wvi, bvr, bvi, 2);

    dim3 ag(NSEQ / 64, BHN);                     // (32, 16)
    attn_kernel<<<ag, 256, ATTN_SMEM>>>((float*)d_out);
}

// round 10
// speedup vs baseline: 1.5558x; 1.0828x over previous
#include <cuda_runtime.h>
#include <cstdint>
#include <math.h>

#define HIDDEN 512
#define HEADS  8
#define DK     64
#define BATCH  2
#define NSEQ   2048
#define MROWS  (BATCH*NSEQ)     // 4096
#define BHN    (BATCH*HEADS)    // 16
#define NORMC  0.125f
#define TK     32               // keys per attention tile
#define NTILE  (NSEQ/TK)        // 64

typedef unsigned long long ull;
typedef unsigned int uint32;

// ---- packed f32x2 helpers (Blackwell FFMA2 path) ----
__device__ __forceinline__ ull bcast2(float x) {
    ull r; asm("mov.b64 %0, {%1,%1};" : "=l"(r) : "f"(x)); return r;
}
__device__ __forceinline__ float2 unpack2(ull v) {
    float2 f; asm("mov.b64 {%0,%1}, %2;" : "=f"(f.x), "=f"(f.y) : "l"(v)); return f;
}
__device__ __forceinline__ ull ffma2(ull a, ull b, ull c) {
    ull d; asm("fma.rn.f32x2 %0, %1, %2, %3;" : "=l"(d) : "l"(a), "l"(b), "l"(c)); return d;
}
__device__ __forceinline__ ull as_ull(float2 v) {
    ull r; asm("mov.b64 %0, {%1,%2};" : "=l"(r) : "f"(v.x), "f"(v.y)); return r;
}
__device__ __forceinline__ uint32 smem_u32(const void* p) {
    return (uint32)__cvta_generic_to_shared(p);
}
__device__ __forceinline__ void cpa16(uint32 dst, const void* src) {
    asm volatile("cp.async.cg.shared.global [%0], [%1], 16;" :: "r"(dst), "l"(src));
}
#define CPA_COMMIT() asm volatile("cp.async.commit_group;")
#define CPA_WAIT(n)  asm volatile("cp.async.wait_group %0;" :: "n"(n))

// Scratch: Q/K/V in [b,h,n,d] layout, complex interleaved. float4 declaration
// guarantees the 16B alignment cp.async requires; proj views them as float2.
__device__ float4 g_q[(size_t)BHN * NSEQ * DK / 2];
__device__ float4 g_k[(size_t)BHN * NSEQ * DK / 2];
__device__ float4 g_v[(size_t)BHN * NSEQ * DK / 2];

// ---------------------------------------------------------------------------
// Projection: Y = X @ W^T + b (complex), FFMA2 inner loop.
// One kernel for all 3 projections (blockIdx.z selects Q/K/V); global tile
// loads are register double-buffered so DRAM/L2 latency overlaps compute.
// ---------------------------------------------------------------------------
__global__ __launch_bounds__(256, 2) void proj_kernel(
    const float* __restrict__ xr, const float* __restrict__ xi,
    const float* __restrict__ Wqr, const float* __restrict__ Wqi,
    const float* __restrict__ bqr, const float* __restrict__ bqi,
    const float* __restrict__ Wkr, const float* __restrict__ Wki,
    const float* __restrict__ bkr, const float* __restrict__ bki,
    const float* __restrict__ Wvr, const float* __restrict__ Wvi,
    const float* __restrict__ bvr, const float* __restrict__ bvi)
{
    __shared__ float2 Asc[64][17];
    __shared__ float2 Bsc[64][17];

    const int which = blockIdx.z;
    const float* Wr = (which == 0) ? Wqr : ((which == 1) ? Wkr : Wvr);
    const float* Wi = (which == 0) ? Wqi : ((which == 1) ? Wki : Wvi);
    const float* br = (which == 0) ? bqr : ((which == 1) ? bkr : bvr);
    const float* bi = (which == 0) ? bqi : ((which == 1) ? bki : bvi);
    float2* out = (float2*)((which == 0) ? g_q : ((which == 1) ? g_k : g_v));

    const int n0 = blockIdx.x * 64;
    const int m0 = blockIdx.y * 64;
    const int tid = threadIdx.x;
    const int tx = tid & 15, ty = tid >> 4;

    // per-thread staging slots (register double-buffer)
    const int kk_s = tid & 15;
    const int rr0  = tid >> 4;          // rows rr0, rr0+16, rr0+32, rr0+48

    float2 ra[4], rb[4];
    #pragma unroll
    for (int l = 0; l < 4; l++) {
        int rr = rr0 + l * 16;
        size_t ga = (size_t)(m0 + rr) * HIDDEN + kk_s;
        size_t gb = (size_t)(n0 + rr) * HIDDEN + kk_s;
        ra[l] = make_float2(xr[ga], xi[ga]);
        rb[l] = make_float2(Wr[gb], Wi[gb]);
    }

    ull acc1[4][4], acc2[4][4];
    #pragma unroll
    for (int i = 0; i < 4; i++)
        #pragma unroll
        for (int j = 0; j < 4; j++) { acc1[i][j] = 0ULL; acc2[i][j] = 0ULL; }

    for (int k0 = 0; k0 < HIDDEN; k0 += 16) {
        #pragma unroll
        for (int l = 0; l < 4; l++) {
            Asc[rr0 + l*16][kk_s] = ra[l];
            Bsc[rr0 + l*16][kk_s] = rb[l];
        }
        __syncthreads();

        if (k0 + 16 < HIDDEN) {
            #pragma unroll
            for (int l = 0; l < 4; l++) {
                int rr = rr0 + l * 16;
                size_t ga = (size_t)(m0 + rr) * HIDDEN + k0 + 16 + kk_s;
                size_t gb = (size_t)(n0 + rr) * HIDDEN + k0 + 16 + kk_s;
                ra[l] = make_float2(xr[ga], xi[ga]);
                rb[l] = make_float2(Wr[gb], Wi[gb]);
            }
        }

        #pragma unroll
        for (int kk = 0; kk < 16; kk++) {
            ull arr[4], aii[4], w2[4];
            #pragma unroll
            for (int i = 0; i < 4; i++) {
                float2 a = Asc[ty + 16*i][kk];
                arr[i] = bcast2(a.x); aii[i] = bcast2(a.y);
            }
            #pragma unroll
            for (int j = 0; j < 4; j++) w2[j] = as_ull(Bsc[tx + 16*j][kk]);
            #pragma unroll
            for (int i = 0; i < 4; i++)
                #pragma unroll
                for (int j = 0; j < 4; j++) {
                    acc1[i][j] = ffma2(arr[i], w2[j], acc1[i][j]);
                    acc2[i][j] = ffma2(aii[i], w2[j], acc2[i][j]);
                }
        }
        __syncthreads();
    }

    #pragma unroll
    for (int i = 0; i < 4; i++) {
        int m = m0 + ty + 16*i;
        int bb = m >> 11;
        int n  = m & 2047;
        #pragma unroll
        for (int j = 0; j < 4; j++) {
            int col = n0 + tx + 16*j;
            int h = col >> 6, d = col & 63;
            float2 c1 = unpack2(acc1[i][j]), c2 = unpack2(acc2[i][j]);
            float yr = c1.x - c2.y + br[col];
            float yi = c1.y + c2.x + bi[col];
            out[(((size_t)bb * HEADS + h) * NSEQ + n) * DK + d] = make_float2(yr, yi);
        }
    }
}

// ---------------------------------------------------------------------------
// Fused attention: 64 queries x 32-key tiles, cp.async double-buffered K/V,
// 2 CTAs/SM. Packed math:
//   s1 += (qx,qy)*(kx,kx); s2 += (qx,qy)*(ky,ky)
//   re = s1.x - s2.y ; im = s1.y + s2.x
// SMEM (bytes): Qs f4[64*32]=32768 | Ks f4[2][32*33]=33792 |
//               Vs f2[2][32*64]=32768 | Ps f[64*33]=8448  -> 107776 total
// ---------------------------------------------------------------------------
#define KS_STRIDE 33                  // float4 row stride (odd -> conflict-free LDS.128)
#define KS_BUF    (32*KS_STRIDE)      // 1056 float4 per buffer
#define VS_BUF    (32*64)             // 2048 float2 per buffer
#define VS_BUF_BYTES (VS_BUF*8)       // 16384 bytes per V buffer
#define ATTN_SMEM (32768 + 33792 + 32768 + 8448)

__global__ __launch_bounds__(256, 2) void attn_kernel(float* __restrict__ out)
{
    extern __shared__ float smem[];
    float4* Qs = (float4*)smem;                    // [64][32]
    float4* Ks = Qs + 64*32;                       // [2][32][KS_STRIDE]
    float2* Vs = (float2*)(Ks + 2*KS_BUF);         // [2][32][64]
    float*  Ps = (float*)(Vs + 2*VS_BUF);          // [64][33]

    const int bh = blockIdx.y;
    const int n0 = blockIdx.x * 64;
    const int tid = threadIdx.x;
    const int tx = tid & 15, ty = tid >> 4;

    // per-(b,h) base in float4 units (DK complex = 128 floats = 32 float4 per row)
    const float4* qb4 = g_q + ((size_t)bh * NSEQ + n0) * (DK/2);
    const float4* kb4 = g_k + (size_t)bh * NSEQ * (DK/2);
    const float4* vb4 = g_v + (size_t)bh * NSEQ * (DK/2);

    const uint32 qs_b = smem_u32(Qs);
    const uint32 ks_b = smem_u32(Ks);
    const uint32 vs_b = smem_u32(Vs);

    // Prologue: Q (32KB) + tile 0 K/V, one cp.async group
    #pragma unroll
    for (int l = 0; l < 8; l++) {
        int id = tid + l * 256;                    // 0..2047 float4
        cpa16(qs_b + id * 16, qb4 + id);
    }
    {
        #pragma unroll
        for (int l = 0; l < 4; l++) {
            int id = tid + l * 256;                // 0..1023
            int row = id >> 5, dp = id & 31;
            cpa16(ks_b + (row * KS_STRIDE + dp) * 16, kb4 + row * 32 + dp);
            cpa16(vs_b + id * 16, vb4 + id);
        }
    }
    CPA_COMMIT();

    ull o_acc[4][4];
    #pragma unroll
    for (int i = 0; i < 4; i++)
        #pragma unroll
        for (int j = 0; j < 4; j++) o_acc[i][j] = 0ULL;
    float den[4] = {};

    for (int t = 0; t < NTILE; t++) {
        const int cur = t & 1;
        if (t + 1 < NTILE) {
            const int nb = cur ^ 1;
            const float4* kt = kb4 + (size_t)(t + 1) * 1024;
            const float4* vt = vb4 + (size_t)(t + 1) * 1024;
            #pragma unroll
            for (int l = 0; l < 4; l++) {
                int id = tid + l * 256;
                int row = id >> 5, dp = id & 31;
                cpa16(ks_b + (nb * KS_BUF + row * KS_STRIDE + dp) * 16, kt + row * 32 + dp);
                cpa16(vs_b + nb * VS_BUF_BYTES + id * 16, vt + id);
            }
            CPA_COMMIT();
            CPA_WAIT(1);
        } else {
            CPA_WAIT(0);
        }
        __syncthreads();

        // ---- S = Q . K^T (complex, no conj) over 32 keys ----
        ull s1[4][2], s2[4][2];
        #pragma unroll
        for (int i = 0; i < 4; i++)
            #pragma unroll
            for (int j = 0; j < 2; j++) { s1[i][j] = 0ULL; s2[i][j] = 0ULL; }

        const longlong2* Ksc = (const longlong2*)(Ks + cur * KS_BUF);
        const longlong2* Qsc = (const longlong2*)Qs;

        #pragma unroll 4
        for (int dp = 0; dp < 32; dp++) {
            longlong2 q2[4];
            #pragma unroll
            for (int i = 0; i < 4; i++) q2[i] = Qsc[(ty + 16*i) * 32 + dp];

            ull kxx[2][2], kyy[2][2];
            #pragma unroll
            for (int j = 0; j < 2; j++) {
                longlong2 kv = Ksc[(tx + 16*j) * KS_STRIDE + dp];
                float2 k0 = unpack2((ull)kv.x), k1 = unpack2((ull)kv.y);
                kxx[j][0] = bcast2(k0.x); kyy[j][0] = bcast2(k0.y);
                kxx[j][1] = bcast2(k1.x); kyy[j][1] = bcast2(k1.y);
            }
            #pragma unroll
            for (int i = 0; i < 4; i++)
                #pragma unroll
                for (int j = 0; j < 2; j++) {
                    s1[i][j] = ffma2((ull)q2[i].x, kxx[j][0], s1[i][j]);
                    s2[i][j] = ffma2((ull)q2[i].x, kyy[j][0], s2[i][j]);
                    s1[i][j] = ffma2((ull)q2[i].y, kxx[j][1], s1[i][j]);
                    s2[i][j] = ffma2((ull)q2[i].y, kyy[j][1], s2[i][j]);
                }
        }

        // ---- w = exp(|s| * NORM) -> Ps, accumulate denominator ----
        #pragma unroll
        for (int i = 0; i < 4; i++)
            #pragma unroll
            for (int j = 0; j < 2; j++) {
                float2 c1 = unpack2(s1[i][j]), c2 = unpack2(s2[i][j]);
                float sr = c1.x - c2.y;
                float si = c1.y + c2.x;
                float a = sqrtf(sr * sr + si * si) * NORMC;
                float w = __expf(a);
                den[i] += w;
                Ps[(ty + 16*i) * 33 + (tx + 16*j)] = w;
            }
        __syncthreads();

        // ---- O += P @ V ----
        const float2* Vsc = Vs + cur * VS_BUF;
        #pragma unroll 4
        for (int c = 0; c < 32; c++) {
            ull p2[4], vv[4];
            #pragma unroll
            for (int i = 0; i < 4; i++) p2[i] = bcast2(Ps[(ty + 16*i) * 33 + c]);
            #pragma unroll
            for (int j = 0; j < 4; j++) vv[j] = as_ull(Vsc[c * 64 + tx + 16*j]);
            #pragma unroll
            for (int i = 0; i < 4; i++)
                #pragma unroll
                for (int j = 0; j < 4; j++)
                    o_acc[i][j] = ffma2(p2[i], vv[j], o_acc[i][j]);
        }
        __syncthreads();
    }

    // ---- reduce denominator across tx (16 partials per query row) ----
    #pragma unroll
    for (int i = 0; i < 4; i++) Ps[(ty + 16*i) * 17 + tx] = den[i];
    __syncthreads();
    #pragma unroll
    for (int i = 0; i < 4; i++) {
        float s = 0.f;
        #pragma unroll
        for (int tt = 0; tt < 16; tt++) s += Ps[(ty + 16*i) * 17 + tt];
        den[i] = 1.0f / s;
    }

    // ---- output: [B, N, D, 2] fp32 (= float2 per complex element) ----
    const int bb = bh >> 3, h = bh & 7;
    float2* outv = (float2*)out;
    #pragma unroll
    for (int i = 0; i < 4; i++) {
        int n = n0 + ty + 16*i;
        #pragma unroll
        for (int j = 0; j < 4; j++) {
            int d = tx + 16*j;
            float2 oo = unpack2(o_acc[i][j]);
            outv[((size_t)bb * NSEQ + n) * HIDDEN + h * DK + d] =
                make_float2(oo.x * den[i], oo.y * den[i]);
        }
    }
}

extern "C" void kernel_launch(void* const* d_in, const int* in_sizes, int n_in,
                              void* d_out, int out_size)
{
    const float* xr  = (const float*)d_in[0];
    const float* xi  = (const float*)d_in[1];
    const float* Wqr = (const float*)d_in[2];
    const float* Wqi = (const float*)d_in[3];
    const float* bqr = (const float*)d_in[4];
    const float* bqi = (const float*)d_in[5];
    const float* Wkr = (const float*)d_in[6];
    const float* Wki = (const float*)d_in[7];
    const float* bkr = (const float*)d_in[8];
    const float* bki = (const float*)d_in[9];
    const float* Wvr = (const float*)d_in[10];
    const float* Wvi = (const float*)d_in[11];
    const float* bvr = (const float*)d_in[12];
    const float* bvi = (const float*)d_in[13];

    cudaFuncSetAttribute(attn_kernel, cudaFuncAttributeMaxDynamicSharedMemorySize, ATTN_SMEM);

    dim3 pb(256), pg(HIDDEN / 64, MROWS / 64, 3);  // (8, 64, 3) — all projections
    proj_kernel<<<pg, pb>>>(xr, xi,
                            Wqr, Wqi, bqr, bqi,
                            Wkr, Wki, bkr, bki,
                            Wvr, Wvi, bvr, bvi);

    dim3 ag(NSEQ / 64, BHN);                       // (32, 16)
    attn_kernel<<<ag, 256, ATTN_SMEM>>>((float*)d_out);
}

// round 11
// speedup vs baseline: 1.6934x; 1.0884x over previous
#include <cuda_runtime.h>
#include <cstdint>
#include <math.h>

#define HIDDEN 512
#define HEADS  8
#define DK     64
#define BATCH  2
#define NSEQ   2048
#define MROWS  (BATCH*NSEQ)     // 4096
#define BHN    (BATCH*HEADS)    // 16
#define NORMC  0.125f
#define TK     32               // keys per attention tile
#define KSPLIT 4                // key-range splits (flash-decoding style)
#define NTILE_S (NSEQ/TK/KSPLIT)   // 16 key tiles per split CTA

typedef unsigned long long ull;
typedef unsigned int uint32;

// ---- packed f32x2 helpers (Blackwell FFMA2 path) ----
__device__ __forceinline__ ull bcast2(float x) {
    ull r; asm("mov.b64 %0, {%1,%1};" : "=l"(r) : "f"(x)); return r;
}
__device__ __forceinline__ float2 unpack2(ull v) {
    float2 f; asm("mov.b64 {%0,%1}, %2;" : "=f"(f.x), "=f"(f.y) : "l"(v)); return f;
}
__device__ __forceinline__ ull ffma2(ull a, ull b, ull c) {
    ull d; asm("fma.rn.f32x2 %0, %1, %2, %3;" : "=l"(d) : "l"(a), "l"(b), "l"(c)); return d;
}
__device__ __forceinline__ ull as_ull(float2 v) {
    ull r; asm("mov.b64 %0, {%1,%2};" : "=l"(r) : "f"(v.x), "f"(v.y)); return r;
}
__device__ __forceinline__ uint32 smem_u32(const void* p) {
    return (uint32)__cvta_generic_to_shared(p);
}
__device__ __forceinline__ void cpa16(uint32 dst, const void* src) {
    asm volatile("cp.async.cg.shared.global [%0], [%1], 16;" :: "r"(dst), "l"(src));
}
#define CPA_COMMIT() asm volatile("cp.async.commit_group;")
#define CPA_WAIT(n)  asm volatile("cp.async.wait_group %0;" :: "n"(n))

// Scratch: Q/K/V in [b,h,n,d] layout, complex interleaved (16B-aligned).
__device__ float4 g_q[(size_t)BHN * NSEQ * DK / 2];
__device__ float4 g_k[(size_t)BHN * NSEQ * DK / 2];
__device__ float4 g_v[(size_t)BHN * NSEQ * DK / 2];
// Split-KV partials: raw O and denominator per split.
__device__ float2 g_po[(size_t)KSPLIT * BHN * NSEQ * DK];     // 67MB
__device__ float  g_pden[(size_t)KSPLIT * BHN * NSEQ];        // 512K floats

// ---------------------------------------------------------------------------
// Projection: Y = X @ W^T + b (complex), FFMA2 inner loop, all 3 in one grid
// (blockIdx.z), register double-buffered global loads. (~81% of fma roofline)
// ---------------------------------------------------------------------------
__global__ __launch_bounds__(256, 2) void proj_kernel(
    const float* __restrict__ xr, const float* __restrict__ xi,
    const float* __restrict__ Wqr, const float* __restrict__ Wqi,
    const float* __restrict__ bqr, const float* __restrict__ bqi,
    const float* __restrict__ Wkr, const float* __restrict__ Wki,
    const float* __restrict__ bkr, const float* __restrict__ bki,
    const float* __restrict__ Wvr, const float* __restrict__ Wvi,
    const float* __restrict__ bvr, const float* __restrict__ bvi)
{
    __shared__ float2 Asc[64][17];
    __shared__ float2 Bsc[64][17];

    const int which = blockIdx.z;
    const float* Wr = (which == 0) ? Wqr : ((which == 1) ? Wkr : Wvr);
    const float* Wi = (which == 0) ? Wqi : ((which == 1) ? Wki : Wvi);
    const float* br = (which == 0) ? bqr : ((which == 1) ? bkr : bvr);
    const float* bi = (which == 0) ? bqi : ((which == 1) ? bki : bvi);
    float2* out = (float2*)((which == 0) ? g_q : ((which == 1) ? g_k : g_v));

    const int n0 = blockIdx.x * 64;
    const int m0 = blockIdx.y * 64;
    const int tid = threadIdx.x;
    const int tx = tid & 15, ty = tid >> 4;

    const int kk_s = tid & 15;
    const int rr0  = tid >> 4;

    float2 ra[4], rb[4];
    #pragma unroll
    for (int l = 0; l < 4; l++) {
        int rr = rr0 + l * 16;
        size_t ga = (size_t)(m0 + rr) * HIDDEN + kk_s;
        size_t gb = (size_t)(n0 + rr) * HIDDEN + kk_s;
        ra[l] = make_float2(xr[ga], xi[ga]);
        rb[l] = make_float2(Wr[gb], Wi[gb]);
    }

    ull acc1[4][4], acc2[4][4];
    #pragma unroll
    for (int i = 0; i < 4; i++)
        #pragma unroll
        for (int j = 0; j < 4; j++) { acc1[i][j] = 0ULL; acc2[i][j] = 0ULL; }

    for (int k0 = 0; k0 < HIDDEN; k0 += 16) {
        #pragma unroll
        for (int l = 0; l < 4; l++) {
            Asc[rr0 + l*16][kk_s] = ra[l];
            Bsc[rr0 + l*16][kk_s] = rb[l];
        }
        __syncthreads();

        if (k0 + 16 < HIDDEN) {
            #pragma unroll
            for (int l = 0; l < 4; l++) {
                int rr = rr0 + l * 16;
                size_t ga = (size_t)(m0 + rr) * HIDDEN + k0 + 16 + kk_s;
                size_t gb = (size_t)(n0 + rr) * HIDDEN + k0 + 16 + kk_s;
                ra[l] = make_float2(xr[ga], xi[ga]);
                rb[l] = make_float2(Wr[gb], Wi[gb]);
            }
        }

        #pragma unroll
        for (int kk = 0; kk < 16; kk++) {
            ull arr[4], aii[4], w2[4];
            #pragma unroll
            for (int i = 0; i < 4; i++) {
                float2 a = Asc[ty + 16*i][kk];
                arr[i] = bcast2(a.x); aii[i] = bcast2(a.y);
            }
            #pragma unroll
            for (int j = 0; j < 4; j++) w2[j] = as_ull(Bsc[tx + 16*j][kk]);
            #pragma unroll
            for (int i = 0; i < 4; i++)
                #pragma unroll
                for (int j = 0; j < 4; j++) {
                    acc1[i][j] = ffma2(arr[i], w2[j], acc1[i][j]);
                    acc2[i][j] = ffma2(aii[i], w2[j], acc2[i][j]);
                }
        }
        __syncthreads();
    }

    #pragma unroll
    for (int i = 0; i < 4; i++) {
        int m = m0 + ty + 16*i;
        int bb = m >> 11;
        int n  = m & 2047;
        #pragma unroll
        for (int j = 0; j < 4; j++) {
            int col = n0 + tx + 16*j;
            int h = col >> 6, d = col & 63;
            float2 c1 = unpack2(acc1[i][j]), c2 = unpack2(acc2[i][j]);
            float yr = c1.x - c2.y + br[col];
            float yi = c1.y + c2.x + bi[col];
            out[(((size_t)bb * HEADS + h) * NSEQ + n) * DK + d] = make_float2(yr, yi);
        }
    }
}

// ---------------------------------------------------------------------------
// Attention partial (split-KV): CTA = 64 queries x 512 keys of one (b,h).
// Writes RAW O-accumulator and softmax denominator; combine is linear
// (no max-subtraction needed) in a tiny reduce kernel.
// grid = (32 qtiles, 16 bh, KSPLIT) = 2048 CTAs -> last wave 92% full.
// ---------------------------------------------------------------------------
#define KS_STRIDE 33                  // float4 row stride (odd -> conflict-free LDS.128)
#define KS_BUF    (32*KS_STRIDE)      // float4 per K buffer
#define VS_BUF    (32*64)             // float2 per V buffer
#define VS_BUF_BYTES (VS_BUF*8)
#define ATTN_SMEM (32768 + 33792 + 32768 + 8448)

__global__ __launch_bounds__(256, 2) void attn_partial_kernel()
{
    extern __shared__ float smem[];
    float4* Qs = (float4*)smem;                    // [64][32]
    float4* Ks = Qs + 64*32;                       // [2][32][KS_STRIDE]
    float2* Vs = (float2*)(Ks + 2*KS_BUF);         // [2][32][64]
    float*  Ps = (float*)(Vs + 2*VS_BUF);          // [64][33]

    const int bh = blockIdx.y;
    const int n0 = blockIdx.x * 64;
    const int sp = blockIdx.z;                     // key-range split
    const int tid = threadIdx.x;
    const int tx = tid & 15, ty = tid >> 4;

    const float4* qb4 = g_q + ((size_t)bh * NSEQ + n0) * (DK/2);
    // key base offset by split: each split covers NTILE_S tiles of TK keys
    const float4* kb4 = g_k + (size_t)bh * NSEQ * (DK/2) + (size_t)sp * NTILE_S * 1024;
    const float4* vb4 = g_v + (size_t)bh * NSEQ * (DK/2) + (size_t)sp * NTILE_S * 1024;

    const uint32 qs_b = smem_u32(Qs);
    const uint32 ks_b = smem_u32(Ks);
    const uint32 vs_b = smem_u32(Vs);

    // Prologue: Q (32KB) + tile 0 K/V
    #pragma unroll
    for (int l = 0; l < 8; l++) {
        int id = tid + l * 256;
        cpa16(qs_b + id * 16, qb4 + id);
    }
    #pragma unroll
    for (int l = 0; l < 4; l++) {
        int id = tid + l * 256;
        int row = id >> 5, dp = id & 31;
        cpa16(ks_b + (row * KS_STRIDE + dp) * 16, kb4 + row * 32 + dp);
        cpa16(vs_b + id * 16, vb4 + id);
    }
    CPA_COMMIT();

    ull o_acc[4][4];
    #pragma unroll
    for (int i = 0; i < 4; i++)
        #pragma unroll
        for (int j = 0; j < 4; j++) o_acc[i][j] = 0ULL;
    float den[4] = {};

    for (int t = 0; t < NTILE_S; t++) {
        const int cur = t & 1;
        if (t + 1 < NTILE_S) {
            const int nb = cur ^ 1;
            const float4* kt = kb4 + (size_t)(t + 1) * 1024;
            const float4* vt = vb4 + (size_t)(t + 1) * 1024;
            #pragma unroll
            for (int l = 0; l < 4; l++) {
                int id = tid + l * 256;
                int row = id >> 5, dp = id & 31;
                cpa16(ks_b + (nb * KS_BUF + row * KS_STRIDE + dp) * 16, kt + row * 32 + dp);
                cpa16(vs_b + nb * VS_BUF_BYTES + id * 16, vt + id);
            }
            CPA_COMMIT();
            CPA_WAIT(1);
        } else {
            CPA_WAIT(0);
        }
        __syncthreads();

        // ---- S = Q . K^T (complex, no conj) over 32 keys ----
        ull s1[4][2], s2[4][2];
        #pragma unroll
        for (int i = 0; i < 4; i++)
            #pragma unroll
            for (int j = 0; j < 2; j++) { s1[i][j] = 0ULL; s2[i][j] = 0ULL; }

        const longlong2* Ksc = (const longlong2*)(Ks + cur * KS_BUF);
        const longlong2* Qsc = (const longlong2*)Qs;

        #pragma unroll 4
        for (int dp = 0; dp < 32; dp++) {
            longlong2 q2[4];
            #pragma unroll
            for (int i = 0; i < 4; i++) q2[i] = Qsc[(ty + 16*i) * 32 + dp];

            ull kxx[2][2], kyy[2][2];
            #pragma unroll
            for (int j = 0; j < 2; j++) {
                longlong2 kv = Ksc[(tx + 16*j) * KS_STRIDE + dp];
                float2 k0 = unpack2((ull)kv.x), k1 = unpack2((ull)kv.y);
                kxx[j][0] = bcast2(k0.x); kyy[j][0] = bcast2(k0.y);
                kxx[j][1] = bcast2(k1.x); kyy[j][1] = bcast2(k1.y);
            }
            #pragma unroll
            for (int i = 0; i < 4; i++)
                #pragma unroll
                for (int j = 0; j < 2; j++) {
                    s1[i][j] = ffma2((ull)q2[i].x, kxx[j][0], s1[i][j]);
                    s2[i][j] = ffma2((ull)q2[i].x, kyy[j][0], s2[i][j]);
                    s1[i][j] = ffma2((ull)q2[i].y, kxx[j][1], s1[i][j]);
                    s2[i][j] = ffma2((ull)q2[i].y, kyy[j][1], s2[i][j]);
                }
        }

        // ---- w = exp(|s| * NORM) -> Ps, accumulate denominator ----
        #pragma unroll
        for (int i = 0; i < 4; i++)
            #pragma unroll
            for (int j = 0; j < 2; j++) {
                float2 c1 = unpack2(s1[i][j]), c2 = unpack2(s2[i][j]);
                float sr = c1.x - c2.y;
                float si = c1.y + c2.x;
                float a = sqrtf(sr * sr + si * si) * NORMC;
                float w = __expf(a);
                den[i] += w;
                Ps[(ty + 16*i) * 33 + (tx + 16*j)] = w;
            }
        __syncthreads();

        // ---- O += P @ V ----
        const float2* Vsc = Vs + cur * VS_BUF;
        #pragma unroll 4
        for (int c = 0; c < 32; c++) {
            ull p2[4], vv[4];
            #pragma unroll
            for (int i = 0; i < 4; i++) p2[i] = bcast2(Ps[(ty + 16*i) * 33 + c]);
            #pragma unroll
            for (int j = 0; j < 4; j++) vv[j] = as_ull(Vsc[c * 64 + tx + 16*j]);
            #pragma unroll
            for (int i = 0; i < 4; i++)
                #pragma unroll
                for (int j = 0; j < 4; j++)
                    o_acc[i][j] = ffma2(p2[i], vv[j], o_acc[i][j]);
        }
        __syncthreads();
    }

    // ---- reduce partial denominator across tx, write partials ----
    #pragma unroll
    for (int i = 0; i < 4; i++) Ps[(ty + 16*i) * 17 + tx] = den[i];
    __syncthreads();
    #pragma unroll
    for (int i = 0; i < 4; i++) {
        float s = 0.f;
        #pragma unroll
        for (int tt = 0; tt < 16; tt++) s += Ps[(ty + 16*i) * 17 + tt];
        den[i] = s;
    }

    float2* po = g_po + (((size_t)sp * BHN + bh) * NSEQ + n0) * DK;
    float*  pd = g_pden + ((size_t)sp * BHN + bh) * NSEQ + n0;

    #pragma unroll
    for (int i = 0; i < 4; i++) {
        int nl = ty + 16*i;                       // local query row
        if (tx == 0) pd[nl] = den[i];
        #pragma unroll
        for (int j = 0; j < 4; j++) {
            int d = tx + 16*j;
            po[(size_t)nl * DK + d] = unpack2(o_acc[i][j]);
        }
    }
}

// ---------------------------------------------------------------------------
// Combine: out[b,n,h,d] = sum_s o_s / sum_s den_s. Output layout [B,N,D,2].
// ---------------------------------------------------------------------------
__global__ __launch_bounds__(256) void reduce_kernel(float* __restrict__ out)
{
    const size_t idx = (size_t)blockIdx.x * 256 + threadIdx.x;   // complex elem
    // idx over [B][N][H][DK]
    const int d  = idx & 63;
    const int h  = (idx >> 6) & 7;
    const int n  = (idx >> 9) & 2047;
    const int b  = (int)(idx >> 20);
    const int bh = b * HEADS + h;

    float2 o = make_float2(0.f, 0.f);
    float dsum = 0.f;
    #pragma unroll
    for (int s = 0; s < KSPLIT; s++) {
        float2 p = g_po[(((size_t)s * BHN + bh) * NSEQ + n) * DK + d];
        o.x += p.x; o.y += p.y;
        dsum += g_pden[((size_t)s * BHN + bh) * NSEQ + n];
    }
    float inv = 1.0f / dsum;
    ((float2*)out)[idx] = make_float2(o.x * inv, o.y * inv);
}

extern "C" void kernel_launch(void* const* d_in, const int* in_sizes, int n_in,
                              void* d_out, int out_size)
{
    const float* xr  = (const float*)d_in[0];
    const float* xi  = (const float*)d_in[1];
    const float* Wqr = (const float*)d_in[2];
    const float* Wqi = (const float*)d_in[3];
    const float* bqr = (const float*)d_in[4];
    const float* bqi = (const float*)d_in[5];
    const float* Wkr = (const float*)d_in[6];
    const float* Wki = (const float*)d_in[7];
    const float* bkr = (const float*)d_in[8];
    const float* bki = (const float*)d_in[9];
    const float* Wvr = (const float*)d_in[10];
    const float* Wvi = (const float*)d_in[11];
    const float* bvr = (const float*)d_in[12];
    const float* bvi = (const float*)d_in[13];

    cudaFuncSetAttribute(attn_partial_kernel,
                         cudaFuncAttributeMaxDynamicSharedMemorySize, ATTN_SMEM);

    dim3 pb(256), pg(HIDDEN / 64, MROWS / 64, 3);  // (8, 64, 3)
    proj_kernel<<<pg, pb>>>(xr, xi,
                            Wqr, Wqi, bqr, bqi,
                            Wkr, Wki, bkr, bki,
                            Wvr, Wvi, bvr, bvi);

    dim3 ag(NSEQ / 64, BHN, KSPLIT);               // (32, 16, 4) = 2048 CTAs
    attn_partial_kernel<<<ag, 256, ATTN_SMEM>>>();

    const size_t n_complex = (size_t)MROWS * HIDDEN;          // 2M
    reduce_kernel<<<(unsigned)(n_complex / 256), 256>>>((float*)d_out);
}